// round 1
// baseline (speedup 1.0000x reference)
#include <cuda_runtime.h>
#include <math.h>

// ---------------------------------------------------------------------------
// Problem constants
// ---------------------------------------------------------------------------
#define BATCH 2048
#define SEQT  20
#define M_TOK (BATCH*SEQT)   // 40960 tokens
#define DIM_D 2048
#define DIM_E 256
#define DIM_HID 1024
#define NHEAD 4
#define HEADD 64
#define NCLS  1000
#define NLAYER 2

// ---------------------------------------------------------------------------
// Scratch (static __device__ globals: no allocation allowed in kernel_launch)
// ---------------------------------------------------------------------------
__device__ float g_buf1[(size_t)M_TOK * 1024];  // h1 / qkv / ff1 / out_proj tmp
__device__ float g_buf2[(size_t)M_TOK * 256];   // h2 / attn out / ff2 tmp / normed flat
__device__ float g_hst [(size_t)M_TOK * 256];   // hidden state h
__device__ float g_wn  [(size_t)NCLS  * 256];   // normalized head weights

// ---------------------------------------------------------------------------
// Helpers
// ---------------------------------------------------------------------------
__device__ __forceinline__ float geluf(float x) {
    // exact (erf) GELU, matches jax.nn.gelu(approximate=False)
    return 0.5f * x * (1.0f + erff(x * 0.7071067811865475f));
}
__device__ __forceinline__ float warp_sum(float v) {
    #pragma unroll
    for (int o = 16; o; o >>= 1) v += __shfl_xor_sync(0xffffffffu, v, o);
    return v;
}

// ---------------------------------------------------------------------------
// Generic SGEMM:  C[M,N] = A[M,K] @ W[N,K]^T (+ bias)  with epilogue
//   EPI 0: +bias, EPI 1: gelu(+bias), EPI 2: *scale (no bias)
// BM=BN=128, BK=8, 8x8 per thread, 256 threads. M must be a multiple of 128,
// K a multiple of 8; N only needs to be a multiple of 4 (guarded tiles).
// ---------------------------------------------------------------------------
template<int EPI>
__global__ __launch_bounds__(256, 2)
void sgemm_nt(const float* __restrict__ A, const float* __restrict__ W,
              const float* __restrict__ bias, float* __restrict__ C,
              int M, int N, int K, float scale)
{
    __shared__ float As[8][128];
    __shared__ float Ws[8][128];

    const int tid = threadIdx.x;
    const int bm  = blockIdx.y * 128;
    const int bn  = blockIdx.x * 128;
    const int lr  = tid >> 1;            // 0..127 : row within tile for loads
    const int lc  = (tid & 1) << 2;      // 0 or 4 : k-offset for float4 load
    const int ty  = tid >> 4;            // 0..15
    const int tx  = tid & 15;            // 0..15

    float acc[8][8];
    #pragma unroll
    for (int i = 0; i < 8; i++)
        #pragma unroll
        for (int j = 0; j < 8; j++) acc[i][j] = 0.f;

    const float* Ap = A + (size_t)(bm + lr) * K + lc;
    const bool wok  = (bn + lr) < N;
    const float* Wp = W + (size_t)(wok ? (bn + lr) : 0) * K + lc;

    for (int k0 = 0; k0 < K; k0 += 8) {
        float4 a = *(const float4*)(Ap + k0);
        float4 w = wok ? *(const float4*)(Wp + k0) : make_float4(0.f, 0.f, 0.f, 0.f);
        As[lc + 0][lr] = a.x; As[lc + 1][lr] = a.y;
        As[lc + 2][lr] = a.z; As[lc + 3][lr] = a.w;
        Ws[lc + 0][lr] = w.x; Ws[lc + 1][lr] = w.y;
        Ws[lc + 2][lr] = w.z; Ws[lc + 3][lr] = w.w;
        __syncthreads();
        #pragma unroll
        for (int kk = 0; kk < 8; kk++) {
            float ra[8], rw[8];
            #pragma unroll
            for (int i = 0; i < 8; i++) ra[i] = As[kk][ty * 8 + i];
            #pragma unroll
            for (int j = 0; j < 8; j++) rw[j] = Ws[kk][tx * 8 + j];
            #pragma unroll
            for (int i = 0; i < 8; i++)
                #pragma unroll
                for (int j = 0; j < 8; j++) acc[i][j] += ra[i] * rw[j];
        }
        __syncthreads();
    }

    const int colbase = bn + tx * 8;
    float bv[8];
    #pragma unroll
    for (int j = 0; j < 8; j++) {
        int col = colbase + j;
        bv[j] = (bias != nullptr && col < N) ? bias[col] : 0.f;
    }
    #pragma unroll
    for (int i = 0; i < 8; i++) {
        int row = bm + ty * 8 + i;
        float* cp = C + (size_t)row * N;
        #pragma unroll
        for (int g = 0; g < 2; g++) {
            int c0 = colbase + g * 4;
            if (c0 < N) {   // N is always a multiple of 4 -> group fully in/out
                float t0 = acc[i][g * 4 + 0] + bv[g * 4 + 0];
                float t1 = acc[i][g * 4 + 1] + bv[g * 4 + 1];
                float t2 = acc[i][g * 4 + 2] + bv[g * 4 + 2];
                float t3 = acc[i][g * 4 + 3] + bv[g * 4 + 3];
                if (EPI == 1) { t0 = geluf(t0); t1 = geluf(t1); t2 = geluf(t2); t3 = geluf(t3); }
                if (EPI == 2) { t0 *= scale; t1 *= scale; t2 *= scale; t3 *= scale; }
                float4 v; v.x = t0; v.y = t1; v.z = t2; v.w = t3;
                *(float4*)(cp + c0) = v;
            }
        }
    }
}

// ---------------------------------------------------------------------------
// LN + GELU over rows of 1024 (in-place). One block (256 thr) per row.
// ---------------------------------------------------------------------------
__global__ void ln_gelu_1024(float* __restrict__ buf,
                             const float* __restrict__ w,
                             const float* __restrict__ b)
{
    int row = blockIdx.x;
    float4* p = (float4*)(buf + (size_t)row * 1024);
    int tid = threadIdx.x;
    float4 x = p[tid];
    float s  = x.x + x.y + x.z + x.w;
    float ss = x.x * x.x + x.y * x.y + x.z * x.z + x.w * x.w;
    __shared__ float sh[2][8];
    float ws_ = warp_sum(s), wss = warp_sum(ss);
    if ((tid & 31) == 0) { sh[0][tid >> 5] = ws_; sh[1][tid >> 5] = wss; }
    __syncthreads();
    float tot = 0.f, tot2 = 0.f;
    #pragma unroll
    for (int i = 0; i < 8; i++) { tot += sh[0][i]; tot2 += sh[1][i]; }
    float mean = tot * (1.f / 1024.f);
    float var  = tot2 * (1.f / 1024.f) - mean * mean;
    float rstd = rsqrtf(var + 1e-6f);
    float4 wv = ((const float4*)w)[tid];
    float4 bv = ((const float4*)b)[tid];
    x.x = geluf((x.x - mean) * rstd * wv.x + bv.x);
    x.y = geluf((x.y - mean) * rstd * wv.y + bv.y);
    x.z = geluf((x.z - mean) * rstd * wv.z + bv.z);
    x.w = geluf((x.w - mean) * rstd * wv.w + bv.w);
    p[tid] = x;
}

// ---------------------------------------------------------------------------
// LN over rows of 256 + sincos positional encoding, src -> dst.
// Warp per row; block = 8 warps.
// ---------------------------------------------------------------------------
__global__ void ln_pe_256(const float* __restrict__ src, float* __restrict__ dst,
                          const float* __restrict__ w, const float* __restrict__ b)
{
    int row  = blockIdx.x * 8 + (threadIdx.x >> 5);
    int lane = threadIdx.x & 31;
    const float* x = src + (size_t)row * 256;
    float v[8], s = 0.f, ss = 0.f;
    #pragma unroll
    for (int i = 0; i < 8; i++) {
        v[i] = x[lane + 32 * i];
        s += v[i]; ss += v[i] * v[i];
    }
    s = warp_sum(s); ss = warp_sum(ss);
    float mean = s * (1.f / 256.f);
    float var  = ss * (1.f / 256.f) - mean * mean;
    float rstd = rsqrtf(var + 1e-6f);
    int t = row % SEQT;
    float* o = dst + (size_t)row * 256;
    #pragma unroll
    for (int i = 0; i < 8; i++) {
        int c = lane + 32 * i;
        int j = c & ~1;  // even index of the sin/cos pair
        float ang = (float)t * expf((float)j * (-9.210340371976184f / 256.f));
        float pe  = (c & 1) ? cosf(ang) : sinf(ang);
        o[c] = (v[i] - mean) * rstd * w[c] + b[c] + pe;
    }
}

// ---------------------------------------------------------------------------
// Residual add + LN over rows of 256 (in-place on h). Warp per row.
// ---------------------------------------------------------------------------
__global__ void resln_256(float* __restrict__ h, const float* __restrict__ r,
                          const float* __restrict__ w, const float* __restrict__ b)
{
    int row  = blockIdx.x * 8 + (threadIdx.x >> 5);
    int lane = threadIdx.x & 31;
    float* hp = h + (size_t)row * 256;
    const float* rp = r + (size_t)row * 256;
    float v[8], s = 0.f, ss = 0.f;
    #pragma unroll
    for (int i = 0; i < 8; i++) {
        int c = lane + 32 * i;
        v[i] = hp[c] + rp[c];
        s += v[i]; ss += v[i] * v[i];
    }
    s = warp_sum(s); ss = warp_sum(ss);
    float mean = s * (1.f / 256.f);
    float var  = ss * (1.f / 256.f) - mean * mean;
    float rstd = rsqrtf(var + 1e-6f);
    #pragma unroll
    for (int i = 0; i < 8; i++) {
        int c = lane + 32 * i;
        hp[c] = (v[i] - mean) * rstd * w[c] + b[c];
    }
}

// ---------------------------------------------------------------------------
// Row-wise L2 normalize (rows of 256), src -> dst. Warp per row, guarded.
// ---------------------------------------------------------------------------
__global__ void norm_rows_256(const float* __restrict__ src, float* __restrict__ dst,
                              int nrows)
{
    int row  = blockIdx.x * 8 + (threadIdx.x >> 5);
    int lane = threadIdx.x & 31;
    if (row >= nrows) return;
    const float* x = src + (size_t)row * 256;
    float v[8], ss = 0.f;
    #pragma unroll
    for (int i = 0; i < 8; i++) { v[i] = x[lane + 32 * i]; ss += v[i] * v[i]; }
    ss = warp_sum(ss);
    float inv = 1.f / fmaxf(sqrtf(ss), 1e-12f);
    float* o = dst + (size_t)row * 256;
    #pragma unroll
    for (int i = 0; i < 8; i++) o[lane + 32 * i] = v[i] * inv;
}

// ---------------------------------------------------------------------------
// Causal attention for T=20, hd=64. One block per (batch, head), 256 threads.
// qkv layout: [M, 768] rows, q at +head*64, k at +256, v at +512.
// Output layout: [M, 256] ([B,T,H,hd] flattened).
// ---------------------------------------------------------------------------
__global__ void attn_kernel(const float* __restrict__ qkv, float* __restrict__ out)
{
    int bh = blockIdx.x;
    int bidx = bh / NHEAD;
    int hh   = bh % NHEAD;
    __shared__ float q[SEQT][HEADD];
    __shared__ float k[SEQT][HEADD];
    __shared__ float v[SEQT][HEADD];
    __shared__ float p[SEQT][SEQT];
    int tid = threadIdx.x;

    for (int idx = tid; idx < SEQT * HEADD; idx += 256) {
        int t = idx / HEADD, d = idx % HEADD;
        size_t off = (size_t)(bidx * SEQT + t) * 768 + hh * HEADD + d;
        q[t][d] = qkv[off];
        k[t][d] = qkv[off + 256];
        v[t][d] = qkv[off + 512];
    }
    __syncthreads();

    // scores (scaled), causal
    for (int idx = tid; idx < SEQT * SEQT; idx += 256) {
        int t = idx / SEQT, s = idx % SEQT;
        if (s <= t) {
            float acc = 0.f;
            #pragma unroll
            for (int d = 0; d < HEADD; d++) acc += q[t][d] * k[s][d];
            p[t][s] = acc * 0.125f;   // 1/sqrt(64)
        } else {
            p[t][s] = 0.f;            // unused
        }
    }
    __syncthreads();

    // softmax over s<=t, one thread per row
    if (tid < SEQT) {
        int t = tid;
        float mx = -1e30f;
        for (int s = 0; s <= t; s++) mx = fmaxf(mx, p[t][s]);
        float sum = 0.f;
        for (int s = 0; s <= t; s++) { float e = expf(p[t][s] - mx); p[t][s] = e; sum += e; }
        float inv = 1.f / sum;
        for (int s = 0; s <= t; s++) p[t][s] *= inv;
        for (int s = t + 1; s < SEQT; s++) p[t][s] = 0.f;
    }
    __syncthreads();

    // out = probs @ v
    for (int idx = tid; idx < SEQT * HEADD; idx += 256) {
        int t = idx / HEADD, d = idx % HEADD;
        float acc = 0.f;
        for (int s = 0; s <= t; s++) acc += p[t][s] * v[s][d];
        out[(size_t)(bidx * SEQT + t) * 256 + hh * HEADD + d] = acc;
    }
}

// ---------------------------------------------------------------------------
// Launch
// ---------------------------------------------------------------------------
extern "C" void kernel_launch(void* const* d_in, const int* in_sizes, int n_in,
                              void* d_out, int out_size)
{
    const float* x         = (const float*)d_in[0];
    const float* p1_w      = (const float*)d_in[1];
    const float* p1_b      = (const float*)d_in[2];
    const float* pln1_w    = (const float*)d_in[3];
    const float* pln1_b    = (const float*)d_in[4];
    const float* p2_w      = (const float*)d_in[5];
    const float* pln2_w    = (const float*)d_in[6];
    const float* pln2_b    = (const float*)d_in[7];
    const float* in_proj_w = (const float*)d_in[8];
    const float* in_proj_b = (const float*)d_in[9];
    const float* out_proj_w= (const float*)d_in[10];
    const float* out_proj_b= (const float*)d_in[11];
    const float* ln1_w     = (const float*)d_in[12];
    const float* ln1_b     = (const float*)d_in[13];
    const float* lin1_w    = (const float*)d_in[14];
    const float* lin1_b    = (const float*)d_in[15];
    const float* lin2_w    = (const float*)d_in[16];
    const float* lin2_b    = (const float*)d_in[17];
    const float* ln2_w     = (const float*)d_in[18];
    const float* ln2_b     = (const float*)d_in[19];
    const float* head_w    = (const float*)d_in[20];
    float* out = (float*)d_out;

    float *b1, *b2, *h, *wn;
    cudaGetSymbolAddress((void**)&b1, g_buf1);
    cudaGetSymbolAddress((void**)&b2, g_buf2);
    cudaGetSymbolAddress((void**)&h,  g_hst);
    cudaGetSymbolAddress((void**)&wn, g_wn);

    const int M = M_TOK;
    const dim3 blk(256);
    const int MB = M / 128;  // 320

    // projector
    sgemm_nt<0><<<dim3(1024/128, MB), blk>>>(x, p1_w, p1_b, b1, M, 1024, 2048, 1.f);
    ln_gelu_1024<<<M, blk>>>(b1, pln1_w, pln1_b);
    sgemm_nt<0><<<dim3(256/128, MB), blk>>>(b1, p2_w, nullptr, b2, M, 256, 1024, 1.f);
    ln_pe_256<<<M / 8, blk>>>(b2, h, pln2_w, pln2_b);

    // transformer layers
    for (int i = 0; i < NLAYER; i++) {
        const float* ipw = in_proj_w + (size_t)i * 768 * 256;
        const float* ipb = in_proj_b + (size_t)i * 768;
        const float* opw = out_proj_w + (size_t)i * 256 * 256;
        const float* opb = out_proj_b + (size_t)i * 256;
        const float* l1w = lin1_w + (size_t)i * 1024 * 256;
        const float* l1b = lin1_b + (size_t)i * 1024;
        const float* l2w = lin2_w + (size_t)i * 256 * 1024;
        const float* l2b = lin2_b + (size_t)i * 256;

        sgemm_nt<0><<<dim3(768/128, MB), blk>>>(h, ipw, ipb, b1, M, 768, 256, 1.f);
        attn_kernel<<<BATCH * NHEAD, blk>>>(b1, b2);
        sgemm_nt<0><<<dim3(256/128, MB), blk>>>(b2, opw, opb, b1, M, 256, 256, 1.f);
        resln_256<<<M / 8, blk>>>(h, b1, ln1_w + (size_t)i * 256, ln1_b + (size_t)i * 256);
        sgemm_nt<1><<<dim3(1024/128, MB), blk>>>(h, l1w, l1b, b1, M, 1024, 256, 1.f);
        sgemm_nt<0><<<dim3(256/128, MB), blk>>>(b1, l2w, l2b, b2, M, 256, 1024, 1.f);
        resln_256<<<M / 8, blk>>>(h, b2, ln2_w + (size_t)i * 256, ln2_b + (size_t)i * 256);
    }

    // cosine head
    norm_rows_256<<<M / 8, blk>>>(h, b2, M);
    norm_rows_256<<<(NCLS + 7) / 8, blk>>>(head_w, wn, NCLS);
    sgemm_nt<2><<<dim3((NCLS + 127) / 128, MB), blk>>>(b2, wn, nullptr, out,
                                                       M, NCLS, 256, 10.f /* 1/TAU */);
}

// round 5
// speedup vs baseline: 2.3187x; 2.3187x over previous
#include <cuda_runtime.h>
#include <cuda_bf16.h>
#include <math.h>
#include <stdint.h>

// ---------------------------------------------------------------------------
// Problem constants
// ---------------------------------------------------------------------------
#define BATCH 2048
#define SEQT  20
#define M_TOK (BATCH*SEQT)   // 40960 tokens
#define NHEAD 4
#define HEADD 64
#define NCLS  1000
#define NLAYER 2

// ---------------------------------------------------------------------------
// Scratch
// ---------------------------------------------------------------------------
__device__ float g_buf1[(size_t)M_TOK * 1024];
__device__ float g_buf2[(size_t)M_TOK * 256];
__device__ float g_hst [(size_t)M_TOK * 256];
__device__ float g_wn  [(size_t)NCLS  * 256];

// ---------------------------------------------------------------------------
// Helpers
// ---------------------------------------------------------------------------
__device__ __forceinline__ float geluf(float x) {
    return 0.5f * x * (1.0f + erff(x * 0.7071067811865475f));
}
__device__ __forceinline__ float warp_sum(float v) {
    #pragma unroll
    for (int o = 16; o; o >>= 1) v += __shfl_xor_sync(0xffffffffu, v, o);
    return v;
}
__device__ __forceinline__ uint32_t smem_u32(const void* p) {
    uint32_t a;
    asm("{ .reg .u64 t; cvta.to.shared.u64 t, %1; cvt.u32.u64 %0, t; }" : "=r"(a) : "l"(p));
    return a;
}
__device__ __forceinline__ void ldsm4(uint32_t (&r)[4], uint32_t addr) {
    asm volatile("ldmatrix.sync.aligned.m8n8.x4.shared.b16 {%0,%1,%2,%3}, [%4];"
                 : "=r"(r[0]), "=r"(r[1]), "=r"(r[2]), "=r"(r[3]) : "r"(addr));
}
__device__ __forceinline__ void mma16816(float (&d)[4], const uint32_t (&a)[4],
                                         const uint32_t* b) {
    asm volatile("mma.sync.aligned.m16n8k16.row.col.f32.bf16.bf16.f32 "
                 "{%0,%1,%2,%3}, {%4,%5,%6,%7}, {%8,%9}, {%0,%1,%2,%3};"
                 : "+f"(d[0]), "+f"(d[1]), "+f"(d[2]), "+f"(d[3])
                 : "r"(a[0]), "r"(a[1]), "r"(a[2]), "r"(a[3]),
                   "r"(b[0]), "r"(b[1]));
}

// ---------------------------------------------------------------------------
// Split-bf16 tensor-core GEMM: C[M,N] = A[M,K] @ W[N,K]^T (+bias, epilogue)
//   EPI 0: +bias   EPI 1: gelu(+bias)   EPI 2: *scale (no bias)
// CTA 128x128, K-chunk 32 fp32, 3-pass split (AhWh + AlWh + AhWl),
// 256 threads = 8 warps (4 M x 2 N), warp tile 32x64, mma.m16n8k16 bf16.
// Double-buffered smem, register prefetch. M%128==0, K%32==0, N%2==0.
// ---------------------------------------------------------------------------
// smem per stage: Ah,Al,Wh,Wl each 128 rows x 40 bf16 (32 data + 8 pad) = 10240B
#define ROWB   80            // bytes per smem row (40 bf16)
#define OFF_AH 0
#define OFF_AL 10240
#define OFF_WH 20480
#define OFF_WL 30720
#define STAGE  40960
#define SMEM_DYN (2*STAGE)   // 81920 B

template<int EPI>
__global__ __launch_bounds__(256, 1)
void gemm_mma(const float* __restrict__ A, const float* __restrict__ W,
              const float* __restrict__ bias, float* __restrict__ C,
              int M, int N, int K, float scale)
{
    extern __shared__ __align__(128) char smem[];
    const uint32_t sb = smem_u32(smem);
    const int tid  = threadIdx.x;
    const int wid  = tid >> 5;
    const int lane = tid & 31;
    const int bm = blockIdx.y * 128;
    const int bn = blockIdx.x * 128;
    const int wm = (wid & 3) * 32;     // warp row offset in tile
    const int wn = (wid >> 2) * 64;    // warp col offset in tile

    float acc[2][8][4];
    #pragma unroll
    for (int mi = 0; mi < 2; mi++)
        #pragma unroll
        for (int ni = 0; ni < 8; ni++)
            #pragma unroll
            for (int e = 0; e < 4; e++) acc[mi][ni][e] = 0.f;

    // global load indexing: 4 float4 per thread for A, 4 for W
    // fi = tid + 256*i ; row = fi/8 (8 float4 per 32-float row), c4 = (fi%8)*4
    float4 pa[4], pw[4];
    auto gload = [&](int c) {
        const float* Ab = A + (size_t)bm * K + (c << 5);
        const float* Wb = W + (c << 5);
        #pragma unroll
        for (int i = 0; i < 4; i++) {
            int fi = tid + 256 * i;
            int row = fi >> 3, c4 = (fi & 7) << 2;
            pa[i] = *(const float4*)(Ab + (size_t)row * K + c4);
            int gn = bn + row;
            pw[i] = (gn < N) ? *(const float4*)(Wb + (size_t)gn * K + c4)
                             : make_float4(0.f, 0.f, 0.f, 0.f);
        }
    };
    auto split8 = [&](float4 v, uint2& hi, uint2& lo) {
        __nv_bfloat162 h01 = __floats2bfloat162_rn(v.x, v.y);
        __nv_bfloat162 h23 = __floats2bfloat162_rn(v.z, v.w);
        float2 f01 = __bfloat1622float2(h01);
        float2 f23 = __bfloat1622float2(h23);
        __nv_bfloat162 l01 = __floats2bfloat162_rn(v.x - f01.x, v.y - f01.y);
        __nv_bfloat162 l23 = __floats2bfloat162_rn(v.z - f23.x, v.w - f23.y);
        hi.x = *(uint32_t*)&h01; hi.y = *(uint32_t*)&h23;
        lo.x = *(uint32_t*)&l01; lo.y = *(uint32_t*)&l23;
    };
    auto sstore = [&](int s) {
        char* st = smem + s * STAGE;
        #pragma unroll
        for (int i = 0; i < 4; i++) {
            int fi = tid + 256 * i;
            int row = fi >> 3, c4 = (fi & 7) << 2;
            uint32_t off = row * ROWB + c4 * 2;
            uint2 hi, lo;
            split8(pa[i], hi, lo);
            *(uint2*)(st + OFF_AH + off) = hi;
            *(uint2*)(st + OFF_AL + off) = lo;
            split8(pw[i], hi, lo);
            *(uint2*)(st + OFF_WH + off) = hi;
            *(uint2*)(st + OFF_WL + off) = lo;
        }
    };

    // ldmatrix lane addressing (constant per thread across iterations)
    // A: row = wm + mi*16 + (lane&15), col = k0 + 8*(lane>>4)
    const uint32_t a_row = wm + (lane & 15);
    const uint32_t a_kof = (lane >> 4) << 3;
    // B: row = wn + nj*16 + (lane&7) + 8*((lane>>4)&1), col = k0 + 8*((lane>>3)&1)
    const uint32_t b_row = wn + (lane & 7) + (((lane >> 4) & 1) << 3);
    const uint32_t b_kof = ((lane >> 3) & 1) << 3;

    auto mma_pass = [&](uint32_t a_base, uint32_t w_base) {
        #pragma unroll
        for (int ks = 0; ks < 2; ks++) {
            const uint32_t k0 = ks << 4;
            uint32_t af[2][4];
            #pragma unroll
            for (int mi = 0; mi < 2; mi++)
                ldsm4(af[mi], a_base + (a_row + mi * 16) * ROWB + (k0 + a_kof) * 2);
            uint32_t bf[8][2];
            #pragma unroll
            for (int nj = 0; nj < 4; nj++) {
                uint32_t r[4];
                ldsm4(r, w_base + (b_row + nj * 16) * ROWB + (k0 + b_kof) * 2);
                bf[2*nj][0] = r[0]; bf[2*nj][1] = r[1];
                bf[2*nj+1][0] = r[2]; bf[2*nj+1][1] = r[3];
            }
            #pragma unroll
            for (int mi = 0; mi < 2; mi++)
                #pragma unroll
                for (int ni = 0; ni < 8; ni++)
                    mma16816(acc[mi][ni], af[mi], bf[ni]);
        }
    };

    const int nch = K >> 5;
    gload(0);
    sstore(0);
    __syncthreads();
    for (int c = 0; c < nch; c++) {
        if (c + 1 < nch) gload(c + 1);
        const uint32_t st = sb + (c & 1) * STAGE;
        mma_pass(st + OFF_AH, st + OFF_WH);
        mma_pass(st + OFF_AL, st + OFF_WH);
        mma_pass(st + OFF_AH, st + OFF_WL);
        __syncthreads();
        if (c + 1 < nch) {
            sstore((c + 1) & 1);
            __syncthreads();
        }
    }

    // epilogue
    const int r0 = lane >> 2;
    const int cc0 = (lane & 3) << 1;
    #pragma unroll
    for (int mi = 0; mi < 2; mi++) {
        #pragma unroll
        for (int ni = 0; ni < 8; ni++) {
            int col = bn + wn + ni * 8 + cc0;
            if (col >= N) continue;
            float b0 = 0.f, b1 = 0.f;
            if (EPI != 2 && bias != nullptr) { b0 = bias[col]; b1 = bias[col + 1]; }
            int row = bm + wm + mi * 16 + r0;
            #pragma unroll
            for (int h = 0; h < 2; h++) {
                float t0 = acc[mi][ni][2*h + 0] + b0;
                float t1 = acc[mi][ni][2*h + 1] + b1;
                if (EPI == 1) { t0 = geluf(t0); t1 = geluf(t1); }
                if (EPI == 2) { t0 *= scale; t1 *= scale; }
                float2 o; o.x = t0; o.y = t1;
                *(float2*)(C + (size_t)(row + 8*h) * N + col) = o;
            }
        }
    }
}

// ---------------------------------------------------------------------------
// Elementwise kernels (unchanged from passing baseline)
// ---------------------------------------------------------------------------
__global__ void ln_gelu_1024(float* __restrict__ buf,
                             const float* __restrict__ w,
                             const float* __restrict__ b)
{
    int row = blockIdx.x;
    float4* p = (float4*)(buf + (size_t)row * 1024);
    int tid = threadIdx.x;
    float4 x = p[tid];
    float s  = x.x + x.y + x.z + x.w;
    float ss = x.x*x.x + x.y*x.y + x.z*x.z + x.w*x.w;
    __shared__ float sh[2][8];
    float ws_ = warp_sum(s), wss = warp_sum(ss);
    if ((tid & 31) == 0) { sh[0][tid >> 5] = ws_; sh[1][tid >> 5] = wss; }
    __syncthreads();
    float tot = 0.f, tot2 = 0.f;
    #pragma unroll
    for (int i = 0; i < 8; i++) { tot += sh[0][i]; tot2 += sh[1][i]; }
    float mean = tot * (1.f / 1024.f);
    float var  = tot2 * (1.f / 1024.f) - mean * mean;
    float rstd = rsqrtf(var + 1e-6f);
    float4 wv = ((const float4*)w)[tid];
    float4 bv = ((const float4*)b)[tid];
    x.x = geluf((x.x - mean) * rstd * wv.x + bv.x);
    x.y = geluf((x.y - mean) * rstd * wv.y + bv.y);
    x.z = geluf((x.z - mean) * rstd * wv.z + bv.z);
    x.w = geluf((x.w - mean) * rstd * wv.w + bv.w);
    p[tid] = x;
}

__global__ void ln_pe_256(const float* __restrict__ src, float* __restrict__ dst,
                          const float* __restrict__ w, const float* __restrict__ b)
{
    int row  = blockIdx.x * 8 + (threadIdx.x >> 5);
    int lane = threadIdx.x & 31;
    const float* x = src + (size_t)row * 256;
    float v[8], s = 0.f, ss = 0.f;
    #pragma unroll
    for (int i = 0; i < 8; i++) { v[i] = x[lane + 32*i]; s += v[i]; ss += v[i]*v[i]; }
    s = warp_sum(s); ss = warp_sum(ss);
    float mean = s * (1.f/256.f);
    float var  = ss * (1.f/256.f) - mean*mean;
    float rstd = rsqrtf(var + 1e-6f);
    int t = row % SEQT;
    float* o = dst + (size_t)row * 256;
    #pragma unroll
    for (int i = 0; i < 8; i++) {
        int c = lane + 32*i;
        int j = c & ~1;
        float ang = (float)t * expf((float)j * (-9.210340371976184f / 256.f));
        float pe  = (c & 1) ? cosf(ang) : sinf(ang);
        o[c] = (v[i] - mean) * rstd * w[c] + b[c] + pe;
    }
}

__global__ void resln_256(float* __restrict__ h, const float* __restrict__ r,
                          const float* __restrict__ w, const float* __restrict__ b)
{
    int row  = blockIdx.x * 8 + (threadIdx.x >> 5);
    int lane = threadIdx.x & 31;
    float* hp = h + (size_t)row * 256;
    const float* rp = r + (size_t)row * 256;
    float v[8], s = 0.f, ss = 0.f;
    #pragma unroll
    for (int i = 0; i < 8; i++) {
        int c = lane + 32*i;
        v[i] = hp[c] + rp[c];
        s += v[i]; ss += v[i]*v[i];
    }
    s = warp_sum(s); ss = warp_sum(ss);
    float mean = s * (1.f/256.f);
    float var  = ss * (1.f/256.f) - mean*mean;
    float rstd = rsqrtf(var + 1e-6f);
    #pragma unroll
    for (int i = 0; i < 8; i++) {
        int c = lane + 32*i;
        hp[c] = (v[i] - mean) * rstd * w[c] + b[c];
    }
}

__global__ void norm_rows_256(const float* __restrict__ src, float* __restrict__ dst,
                              int nrows)
{
    int row  = blockIdx.x * 8 + (threadIdx.x >> 5);
    int lane = threadIdx.x & 31;
    if (row >= nrows) return;
    const float* x = src + (size_t)row * 256;
    float v[8], ss = 0.f;
    #pragma unroll
    for (int i = 0; i < 8; i++) { v[i] = x[lane + 32*i]; ss += v[i]*v[i]; }
    ss = warp_sum(ss);
    float inv = 1.f / fmaxf(sqrtf(ss), 1e-12f);
    float* o = dst + (size_t)row * 256;
    #pragma unroll
    for (int i = 0; i < 8; i++) o[lane + 32*i] = v[i] * inv;
}

__global__ void attn_kernel(const float* __restrict__ qkv, float* __restrict__ out)
{
    int bh = blockIdx.x;
    int bidx = bh / NHEAD;
    int hh   = bh % NHEAD;
    __shared__ float q[SEQT][HEADD];
    __shared__ float k[SEQT][HEADD];
    __shared__ float v[SEQT][HEADD];
    __shared__ float p[SEQT][SEQT];
    int tid = threadIdx.x;

    for (int idx = tid; idx < SEQT * HEADD; idx += 256) {
        int t = idx / HEADD, d = idx % HEADD;
        size_t off = (size_t)(bidx * SEQT + t) * 768 + hh * HEADD + d;
        q[t][d] = qkv[off];
        k[t][d] = qkv[off + 256];
        v[t][d] = qkv[off + 512];
    }
    __syncthreads();

    for (int idx = tid; idx < SEQT * SEQT; idx += 256) {
        int t = idx / SEQT, s = idx % SEQT;
        if (s <= t) {
            float acc = 0.f;
            #pragma unroll
            for (int d = 0; d < HEADD; d++) acc += q[t][d] * k[s][d];
            p[t][s] = acc * 0.125f;
        } else p[t][s] = 0.f;
    }
    __syncthreads();

    if (tid < SEQT) {
        int t = tid;
        float mx = -1e30f;
        for (int s = 0; s <= t; s++) mx = fmaxf(mx, p[t][s]);
        float sum = 0.f;
        for (int s = 0; s <= t; s++) { float e = expf(p[t][s] - mx); p[t][s] = e; sum += e; }
        float inv = 1.f / sum;
        for (int s = 0; s <= t; s++) p[t][s] *= inv;
        for (int s = t + 1; s < SEQT; s++) p[t][s] = 0.f;
    }
    __syncthreads();

    for (int idx = tid; idx < SEQT * HEADD; idx += 256) {
        int t = idx / HEADD, d = idx % HEADD;
        float acc = 0.f;
        for (int s = 0; s <= t; s++) acc += p[t][s] * v[s][d];
        out[(size_t)(bidx * SEQT + t) * 256 + hh * HEADD + d] = acc;
    }
}

// ---------------------------------------------------------------------------
// Launch
// ---------------------------------------------------------------------------
extern "C" void kernel_launch(void* const* d_in, const int* in_sizes, int n_in,
                              void* d_out, int out_size)
{
    const float* x         = (const float*)d_in[0];
    const float* p1_w      = (const float*)d_in[1];
    const float* p1_b      = (const float*)d_in[2];
    const float* pln1_w    = (const float*)d_in[3];
    const float* pln1_b    = (const float*)d_in[4];
    const float* p2_w      = (const float*)d_in[5];
    const float* pln2_w    = (const float*)d_in[6];
    const float* pln2_b    = (const float*)d_in[7];
    const float* in_proj_w = (const float*)d_in[8];
    const float* in_proj_b = (const float*)d_in[9];
    const float* out_proj_w= (const float*)d_in[10];
    const float* out_proj_b= (const float*)d_in[11];
    const float* ln1_w     = (const float*)d_in[12];
    const float* ln1_b     = (const float*)d_in[13];
    const float* lin1_w    = (const float*)d_in[14];
    const float* lin1_b    = (const float*)d_in[15];
    const float* lin2_w    = (const float*)d_in[16];
    const float* lin2_b    = (const float*)d_in[17];
    const float* ln2_w     = (const float*)d_in[18];
    const float* ln2_b     = (const float*)d_in[19];
    const float* head_w    = (const float*)d_in[20];
    float* out = (float*)d_out;

    float *b1, *b2, *h, *wn;
    cudaGetSymbolAddress((void**)&b1, g_buf1);
    cudaGetSymbolAddress((void**)&b2, g_buf2);
    cudaGetSymbolAddress((void**)&h,  g_hst);
    cudaGetSymbolAddress((void**)&wn, g_wn);

    cudaFuncSetAttribute(gemm_mma<0>, cudaFuncAttributeMaxDynamicSharedMemorySize, SMEM_DYN);
    cudaFuncSetAttribute(gemm_mma<1>, cudaFuncAttributeMaxDynamicSharedMemorySize, SMEM_DYN);
    cudaFuncSetAttribute(gemm_mma<2>, cudaFuncAttributeMaxDynamicSharedMemorySize, SMEM_DYN);

    const int M = M_TOK;
    const dim3 blk(256);
    const int MB = M / 128;  // 320
    #define GRID(N_) dim3(((N_) + 127) / 128, MB)

    // projector
    gemm_mma<0><<<GRID(1024), blk, SMEM_DYN>>>(x, p1_w, p1_b, b1, M, 1024, 2048, 1.f);
    ln_gelu_1024<<<M, blk>>>(b1, pln1_w, pln1_b);
    gemm_mma<0><<<GRID(256), blk, SMEM_DYN>>>(b1, p2_w, nullptr, b2, M, 256, 1024, 1.f);
    ln_pe_256<<<M / 8, blk>>>(b2, h, pln2_w, pln2_b);

    // transformer layers
    for (int i = 0; i < NLAYER; i++) {
        const float* ipw = in_proj_w + (size_t)i * 768 * 256;
        const float* ipb = in_proj_b + (size_t)i * 768;
        const float* opw = out_proj_w + (size_t)i * 256 * 256;
        const float* opb = out_proj_b + (size_t)i * 256;
        const float* l1w = lin1_w + (size_t)i * 1024 * 256;
        const float* l1b = lin1_b + (size_t)i * 1024;
        const float* l2w = lin2_w + (size_t)i * 256 * 1024;
        const float* l2b = lin2_b + (size_t)i * 256;

        gemm_mma<0><<<GRID(768), blk, SMEM_DYN>>>(h, ipw, ipb, b1, M, 768, 256, 1.f);
        attn_kernel<<<BATCH * NHEAD, blk>>>(b1, b2);
        gemm_mma<0><<<GRID(256), blk, SMEM_DYN>>>(b2, opw, opb, b1, M, 256, 256, 1.f);
        resln_256<<<M / 8, blk>>>(h, b1, ln1_w + (size_t)i * 256, ln1_b + (size_t)i * 256);
        gemm_mma<1><<<GRID(1024), blk, SMEM_DYN>>>(h, l1w, l1b, b1, M, 1024, 256, 1.f);
        gemm_mma<0><<<GRID(256), blk, SMEM_DYN>>>(b1, l2w, l2b, b2, M, 256, 1024, 1.f);
        resln_256<<<M / 8, blk>>>(h, b2, ln2_w + (size_t)i * 256, ln2_b + (size_t)i * 256);
    }

    // cosine head
    norm_rows_256<<<M / 8, blk>>>(h, b2, M);
    norm_rows_256<<<(NCLS + 7) / 8, blk>>>(head_w, wn, NCLS);
    gemm_mma<2><<<GRID(NCLS), blk, SMEM_DYN>>>(b2, wn, nullptr, out, M, NCLS, 256, 10.f);
}